// round 4
// baseline (speedup 1.0000x reference)
#include <cuda_runtime.h>
#include <math.h>

#define BNN   81920
#define NEDGE 327680
#define NT    16

typedef unsigned long long u64;

// ------------------------------ scratch (static device memory; no allocs) ---
__device__ __align__(256) float g_deg[BNN];
__device__ __align__(256) float g_dinv[BNN];
__device__ __align__(256) int   g_rowptr[BNN + 1];
__device__ __align__(256) int   g_fill[BNN];
__device__ __align__(256) int   g_csr_src[NEDGE];
__device__ __align__(256) float g_csr_w[NEDGE];
__device__ __align__(256) float g_P1[BNN * 64];
__device__ __align__(256) float g_P2[BNN * 64];
__device__ __align__(256) float g_Gx[BNN * 192];
__device__ __align__(256) float g_Gh[BNN * 128];
__device__ __align__(256) float g_Ghh[BNN * 64];
__device__ __align__(256) float g_Hst[BNN * 64];
__device__ __align__(256) float g_Zst[BNN * 64];
__device__ __align__(256) float g_HRst[BNN * 64];
__device__ __align__(256) float g_Wx[192 * 192];
__device__ __align__(256) float g_Whp[192 * 128];
__device__ __align__(256) float g_Whhp[192 * 64];
__device__ __align__(256) float g_bxp[192];
__device__ __align__(256) float g_bhp[128];
__device__ __align__(256) float g_bhhp[64];
__device__ __align__(256) float g_M1[4096 * 640];
__device__ __align__(256) float g_M2[4096 * 320];

// ------------------------------ f32x2 helpers (FFMA2 path) ------------------
__device__ __forceinline__ u64 ffma2(u64 a, u64 b, u64 c) {
    u64 d;
    asm("fma.rn.f32x2 %0, %1, %2, %3;" : "=l"(d) : "l"(a), "l"(b), "l"(c));
    return d;
}
__device__ __forceinline__ u64 pack2(float lo, float hi) {
    u64 d;
    asm("mov.b64 %0, {%1, %2};" : "=l"(d) : "f"(lo), "f"(hi));
    return d;
}
__device__ __forceinline__ void unpack2(u64 v, float& lo, float& hi) {
    asm("mov.b64 {%0, %1}, %2;" : "=f"(lo), "=f"(hi) : "l"(v));
}

// ------------------------------ graph preprocessing -------------------------
__global__ void k_deg(const int* __restrict__ src, const float* __restrict__ w) {
    int e = blockIdx.x * 256 + threadIdx.x;
    atomicAdd(&g_deg[src[e]], w[e]);
}

__global__ void k_dinv() {
    int n = blockIdx.x * 256 + threadIdx.x;
    float d = g_deg[n];
    g_dinv[n] = (d > 0.f) ? rsqrtf(d) : 0.f;
}

__global__ void k_count(const int* __restrict__ dst) {
    int e = blockIdx.x * 256 + threadIdx.x;
    atomicAdd(&g_fill[dst[e]], 1);
}

__global__ void k_scan() {  // 1 block, 1024 threads: exclusive scan of g_fill -> g_rowptr
    const int tid = threadIdx.x;
    const int lane = tid & 31;
    const int wp = tid >> 5;
    __shared__ int wsum[32];
    __shared__ int carry;
    if (tid == 0) carry = 0;
    __syncthreads();
    for (int c = 0; c < BNN; c += 1024) {
        int v = g_fill[c + tid];
        int x = v;
#pragma unroll
        for (int off = 1; off < 32; off <<= 1) {
            int nbr = __shfl_up_sync(0xffffffffu, x, off);
            if (lane >= off) x += nbr;
        }
        if (lane == 31) wsum[wp] = x;
        __syncthreads();
        if (wp == 0) {
            int y = wsum[lane];
#pragma unroll
            for (int off = 1; off < 32; off <<= 1) {
                int nbr = __shfl_up_sync(0xffffffffu, y, off);
                if (lane >= off) y += nbr;
            }
            wsum[lane] = y;
        }
        __syncthreads();
        int base = carry + ((wp > 0) ? wsum[wp - 1] : 0);
        g_rowptr[c + tid] = base + x - v;
        __syncthreads();
        if (tid == 1023) carry += wsum[31];
        __syncthreads();
    }
    if (tid == 0) g_rowptr[BNN] = carry;
}

__global__ void k_copyfill() {
    int n = blockIdx.x * 256 + threadIdx.x;
    g_fill[n] = g_rowptr[n];
}

__global__ void k_fillcsr(const int* __restrict__ src, const int* __restrict__ dst,
                          const float* __restrict__ w) {
    int e = blockIdx.x * 256 + threadIdx.x;
    int s = src[e], d = dst[e];
    float wn = -g_dinv[s] * w[e] * g_dinv[d];
    int pos = atomicAdd(&g_fill[d], 1);
    g_csr_src[pos] = s;
    g_csr_w[pos] = wn;
}

// ------------------------------ weight packing ------------------------------
__global__ void k_pack(const float* __restrict__ Wxz, const float* __restrict__ Wxr,
                       const float* __restrict__ Wxh, const float* __restrict__ Whz,
                       const float* __restrict__ Whr, const float* __restrict__ Whh,
                       const float* __restrict__ bxz, const float* __restrict__ bxr,
                       const float* __restrict__ bxh, const float* __restrict__ bhz,
                       const float* __restrict__ bhr, const float* __restrict__ bhh) {
    int i = blockIdx.x * 256 + threadIdx.x;
    if (i < 36864) {                       // Wx [192,192], cols = [z|r|h]
        int row = i / 192, col = i % 192;
        int k = row >> 6, ii = row & 63, g = col >> 6, j = col & 63;
        const float* Wg = (g == 0) ? Wxz : ((g == 1) ? Wxr : Wxh);
        g_Wx[i] = Wg[k * 4096 + ii * 64 + j];
    } else if (i < 61440) {                // Wh [192,128], cols = [z|r]
        int t = i - 36864;
        int row = t / 128, col = t % 128;
        int k = row >> 6, ii = row & 63, g = col >> 6, j = col & 63;
        const float* Wg = g ? Whr : Whz;
        g_Whp[t] = Wg[k * 4096 + ii * 64 + j];
    } else if (i < 73728) {                // Whh [192,64]
        int t = i - 61440;
        int row = t >> 6, col = t & 63;
        int k = row >> 6, ii = row & 63;
        g_Whhp[t] = Whh[k * 4096 + ii * 64 + col];
    } else if (i < 73920) {
        int col = i - 73728;
        int g = col >> 6, j = col & 63;
        g_bxp[col] = (g == 0) ? bxz[j] : ((g == 1) ? bxr[j] : bxh[j]);
    } else if (i < 74048) {
        int col = i - 73920;
        g_bhp[col] = (col < 64) ? bhz[col] : bhr[col - 64];
    } else if (i < 74112) {
        g_bhhp[i - 74048] = bhh[i - 74048];
    }
}

// ------------------------------ sparse propagation --------------------------
// out[n] = alpha * sum_{e into n} w[e]*X[src[e]]   (+ beta*base[n] if beta!=0)
__global__ void k_prop(const float4* __restrict__ X, float4* __restrict__ out,
                       float alpha, const float4* __restrict__ base, float beta) {
    int t = blockIdx.x * 128 + threadIdx.x;
    int node = t >> 4;
    int l = t & 15;
    int s = g_rowptr[node], e = g_rowptr[node + 1];
    float ax = 0.f, ay = 0.f, az = 0.f, aw = 0.f;
    for (int i = s; i < e; i++) {
        int src = g_csr_src[i];
        float w = g_csr_w[i];
        float4 v = X[src * 16 + l];
        ax += w * v.x; ay += w * v.y; az += w * v.z; aw += w * v.w;
    }
    float4 r;
    r.x = alpha * ax; r.y = alpha * ay; r.z = alpha * az; r.w = alpha * aw;
    if (beta != 0.f) {
        float4 b = base[node * 16 + l];
        r.x += beta * b.x; r.y += beta * b.y; r.z += beta * b.z; r.w += beta * b.w;
    }
    out[node * 16 + l] = r;
}

// ------------------------------ tiled SGEMM (f32x2) -------------------------
// THREE: A = [A0|A1|A2] concatenated along K (each [M,64], lda=64), Ktot=192.
// else : A = A0 with lda = K. C[M,N] = act(A@W + bias). BM=128, BN=64, BK=32.
template <bool THREE, bool RELU>
__global__ __launch_bounds__(256) void k_gemm(
    const float* __restrict__ A0, const float* __restrict__ A1,
    const float* __restrict__ A2, int K, const float* __restrict__ W,
    const float* __restrict__ bias, float* __restrict__ C, int N) {
    __shared__ float As[32][132];
    __shared__ float Ws[32][64];
    const int tid = threadIdx.x;
    const int tx = tid & 15;
    const int ty = tid >> 4;
    const int m0 = blockIdx.y * 128;
    const int n0 = blockIdx.x * 64;

    u64 acc[4][4];
#pragma unroll
    for (int i = 0; i < 4; i++)
#pragma unroll
        for (int j = 0; j < 4; j++) acc[i][j] = 0ull;

    const int mload = tid >> 3;
    const int kq = (tid & 7) << 2;
    const int wk = tid >> 4;
    const int wn = (tid & 15) << 2;

    const int nk = THREE ? 6 : (K >> 5);
    for (int kt = 0; kt < nk; kt++) {
        const int k0 = kt << 5;
        const float* Ap;
        int lda, kloc;
        if (THREE) {
            const int bsel = k0 >> 6;
            Ap = (bsel == 0) ? A0 : ((bsel == 1) ? A1 : A2);
            kloc = k0 & 63;
            lda = 64;
        } else {
            Ap = A0; kloc = k0; lda = K;
        }
#pragma unroll
        for (int r = 0; r < 4; r++) {
            float4 v = *reinterpret_cast<const float4*>(
                Ap + (size_t)(m0 + mload + r * 32) * lda + kloc + kq);
            As[kq + 0][mload + r * 32] = v.x;
            As[kq + 1][mload + r * 32] = v.y;
            As[kq + 2][mload + r * 32] = v.z;
            As[kq + 3][mload + r * 32] = v.w;
        }
#pragma unroll
        for (int r = 0; r < 2; r++) {
            float4 v = *reinterpret_cast<const float4*>(
                W + (size_t)(k0 + wk + r * 16) * N + n0 + wn);
            *reinterpret_cast<float4*>(&Ws[wk + r * 16][wn]) = v;
        }
        __syncthreads();
#pragma unroll
        for (int k = 0; k < 32; k++) {
            float4 a0v = *reinterpret_cast<const float4*>(&As[k][ty * 8]);
            float4 a1v = *reinterpret_cast<const float4*>(&As[k][ty * 8 + 4]);
            float4 bv = *reinterpret_cast<const float4*>(&Ws[k][tx * 4]);
            u64 ap[4] = {pack2(a0v.x, a0v.y), pack2(a0v.z, a0v.w),
                         pack2(a1v.x, a1v.y), pack2(a1v.z, a1v.w)};
            u64 bb[4] = {pack2(bv.x, bv.x), pack2(bv.y, bv.y),
                         pack2(bv.z, bv.z), pack2(bv.w, bv.w)};
#pragma unroll
            for (int i = 0; i < 4; i++)
#pragma unroll
                for (int j = 0; j < 4; j++)
                    acc[i][j] = ffma2(ap[i], bb[j], acc[i][j]);
        }
        __syncthreads();
    }

    const int col = n0 + tx * 4;
    float b0 = bias[col], b1 = bias[col + 1], b2 = bias[col + 2], b3 = bias[col + 3];
#pragma unroll
    for (int i = 0; i < 4; i++) {
        float lo0, hi0, lo1, hi1, lo2, hi2, lo3, hi3;
        unpack2(acc[i][0], lo0, hi0);
        unpack2(acc[i][1], lo1, hi1);
        unpack2(acc[i][2], lo2, hi2);
        unpack2(acc[i][3], lo3, hi3);
        const int row = m0 + ty * 8 + i * 2;
        float4 r0 = make_float4(lo0 + b0, lo1 + b1, lo2 + b2, lo3 + b3);
        float4 r1 = make_float4(hi0 + b0, hi1 + b1, hi2 + b2, hi3 + b3);
        if (RELU) {
            r0.x = fmaxf(r0.x, 0.f); r0.y = fmaxf(r0.y, 0.f);
            r0.z = fmaxf(r0.z, 0.f); r0.w = fmaxf(r0.w, 0.f);
            r1.x = fmaxf(r1.x, 0.f); r1.y = fmaxf(r1.y, 0.f);
            r1.z = fmaxf(r1.z, 0.f); r1.w = fmaxf(r1.w, 0.f);
        }
        *reinterpret_cast<float4*>(C + (size_t)row * N + col) = r0;
        *reinterpret_cast<float4*>(C + (size_t)(row + 1) * N + col) = r1;
    }
}

// ------------------------------ GRU gate fusion -----------------------------
__device__ __forceinline__ float sigf(float x) { return 1.f / (1.f + expf(-x)); }

__global__ void k_gateZR() {  // Z = sig(Gx_z+Gh_z); R = sig(Gx_r+Gh_r); HR = H*R
    int i = blockIdx.x * 256 + threadIdx.x;  // over BNN*16 float4s
    int n = i >> 4, l = i & 15;
    const float4* Gx = reinterpret_cast<const float4*>(g_Gx);
    const float4* Gh = reinterpret_cast<const float4*>(g_Gh);
    const float4* H = reinterpret_cast<const float4*>(g_Hst);
    float4* Z = reinterpret_cast<float4*>(g_Zst);
    float4* HR = reinterpret_cast<float4*>(g_HRst);
    float4 gz = Gx[(size_t)n * 48 + l];
    float4 gr = Gx[(size_t)n * 48 + 16 + l];
    float4 hz = Gh[(size_t)n * 32 + l];
    float4 hr = Gh[(size_t)n * 32 + 16 + l];
    float4 h = H[(size_t)n * 16 + l];
    float4 z, r, o;
    z.x = sigf(gz.x + hz.x); z.y = sigf(gz.y + hz.y);
    z.z = sigf(gz.z + hz.z); z.w = sigf(gz.w + hz.w);
    r.x = sigf(gr.x + hr.x); r.y = sigf(gr.y + hr.y);
    r.z = sigf(gr.z + hr.z); r.w = sigf(gr.w + hr.w);
    o.x = h.x * r.x; o.y = h.y * r.y; o.z = h.z * r.z; o.w = h.w * r.w;
    Z[(size_t)n * 16 + l] = z;
    HR[(size_t)n * 16 + l] = o;
}

__global__ void k_gateH() {  // Ht = tanh(Gx_h+Ghh); H = relu(Z*H + (1-Z)*Ht)
    int i = blockIdx.x * 256 + threadIdx.x;
    int n = i >> 4, l = i & 15;
    const float4* Gx = reinterpret_cast<const float4*>(g_Gx);
    const float4* Gg = reinterpret_cast<const float4*>(g_Ghh);
    const float4* Z = reinterpret_cast<const float4*>(g_Zst);
    float4* H = reinterpret_cast<float4*>(g_Hst);
    float4 gh = Gx[(size_t)n * 48 + 32 + l];
    float4 gg = Gg[(size_t)n * 16 + l];
    float4 z = Z[(size_t)n * 16 + l];
    float4 h = H[(size_t)n * 16 + l];
    float4 o;
    float t;
    t = tanhf(gh.x + gg.x); o.x = fmaxf(z.x * h.x + (1.f - z.x) * t, 0.f);
    t = tanhf(gh.y + gg.y); o.y = fmaxf(z.y * h.y + (1.f - z.y) * t, 0.f);
    t = tanhf(gh.z + gg.z); o.z = fmaxf(z.z * h.z + (1.f - z.z) * t, 0.f);
    t = tanhf(gh.w + gg.w); o.w = fmaxf(z.w * h.w + (1.f - z.w) * t, 0.f);
    H[(size_t)n * 16 + l] = o;
}

// ------------------------------ final layer + softmax -----------------------
__global__ void k_out(const float* __restrict__ A, const float* __restrict__ W3,
                      const float* __restrict__ b3, float* __restrict__ out) {
    int warp = threadIdx.x >> 5, lane = threadIdx.x & 31;
    int row = blockIdx.x * 8 + warp;
    float s0 = 0.f, s1 = 0.f;
    for (int k = lane; k < 320; k += 32) {
        float a = A[row * 320 + k];
        s0 += a * W3[k * 2];
        s1 += a * W3[k * 2 + 1];
    }
#pragma unroll
    for (int off = 16; off; off >>= 1) {
        s0 += __shfl_xor_sync(0xffffffffu, s0, off);
        s1 += __shfl_xor_sync(0xffffffffu, s1, off);
    }
    if (lane == 0) {
        float l0 = s0 + b3[0], l1 = s1 + b3[1];
        float m = fmaxf(l0, l1);
        float e0 = expf(l0 - m), e1 = expf(l1 - m);
        float inv = 1.f / (e0 + e1);
        out[row * 2] = e0 * inv;
        out[row * 2 + 1] = e1 * inv;
    }
}

// ------------------------------ launch --------------------------------------
extern "C" void kernel_launch(void* const* d_in, const int* in_sizes, int n_in,
                              void* d_out, int out_size) {
    const float* x = (const float*)d_in[0];
    const int* ei = (const int*)d_in[1];
    const float* ew = (const float*)d_in[2];
    const float* Wxz = (const float*)d_in[3];  const float* bxz = (const float*)d_in[4];
    const float* Whz = (const float*)d_in[5];  const float* bhz = (const float*)d_in[6];
    const float* Wxr = (const float*)d_in[7];  const float* bxr = (const float*)d_in[8];
    const float* Whr = (const float*)d_in[9];  const float* bhr = (const float*)d_in[10];
    const float* Wxh = (const float*)d_in[11]; const float* bxh = (const float*)d_in[12];
    const float* Whh = (const float*)d_in[13]; const float* bhh = (const float*)d_in[14];
    const float* W1 = (const float*)d_in[15];  const float* b1 = (const float*)d_in[16];
    const float* W2 = (const float*)d_in[17];  const float* b2 = (const float*)d_in[18];
    const float* W3 = (const float*)d_in[19];  const float* b3 = (const float*)d_in[20];
    float* out = (float*)d_out;
    const int* src = ei;
    const int* dst = ei + NEDGE;

    float *pDeg, *pP1, *pP2, *pGx, *pGh, *pGhh, *pH, *pM1, *pM2;
    float *pWx, *pWh, *pWhh, *pbx, *pbh, *pbhh, *pHR;
    int* pFill;
    cudaGetSymbolAddress((void**)&pDeg, g_deg);
    cudaGetSymbolAddress((void**)&pFill, g_fill);
    cudaGetSymbolAddress((void**)&pP1, g_P1);
    cudaGetSymbolAddress((void**)&pP2, g_P2);
    cudaGetSymbolAddress((void**)&pGx, g_Gx);
    cudaGetSymbolAddress((void**)&pGh, g_Gh);
    cudaGetSymbolAddress((void**)&pGhh, g_Ghh);
    cudaGetSymbolAddress((void**)&pH, g_Hst);
    cudaGetSymbolAddress((void**)&pHR, g_HRst);
    cudaGetSymbolAddress((void**)&pWx, g_Wx);
    cudaGetSymbolAddress((void**)&pWh, g_Whp);
    cudaGetSymbolAddress((void**)&pWhh, g_Whhp);
    cudaGetSymbolAddress((void**)&pbx, g_bxp);
    cudaGetSymbolAddress((void**)&pbh, g_bhp);
    cudaGetSymbolAddress((void**)&pbhh, g_bhhp);
    cudaGetSymbolAddress((void**)&pM1, g_M1);
    cudaGetSymbolAddress((void**)&pM2, g_M2);

    // ---- preprocessing (per launch; deterministic) ----
    cudaMemsetAsync(pDeg, 0, BNN * sizeof(float));
    cudaMemsetAsync(pFill, 0, BNN * sizeof(int));
    cudaMemsetAsync(pH, 0, (size_t)BNN * 64 * sizeof(float));
    k_deg<<<NEDGE / 256, 256>>>(src, ew);
    k_dinv<<<BNN / 256, 256>>>();
    k_count<<<NEDGE / 256, 256>>>(dst);
    k_scan<<<1, 1024>>>();
    k_copyfill<<<BNN / 256, 256>>>();
    k_fillcsr<<<NEDGE / 256, 256>>>(src, dst, ew);
    k_pack<<<(74112 + 255) / 256, 256>>>(Wxz, Wxr, Wxh, Whz, Whr, Whh,
                                         bxz, bxr, bxh, bhz, bhr, bhh);

    const int propGrid = BNN * 16 / 128;  // 10240
    const int ewGrid = BNN * 16 / 256;    // 5120

    // ---- GConvGRU over T timesteps ----
    for (int t = 0; t < NT; t++) {
        const float* Xt = x + (size_t)t * BNN * 64;
        // X-side Chebyshev basis + fused gate GEMM ([X|LX|2L^2X-X] @ Wx)
        k_prop<<<propGrid, 128>>>((const float4*)Xt, (float4*)pP1, 1.f, nullptr, 0.f);
        k_prop<<<propGrid, 128>>>((const float4*)pP1, (float4*)pP2, 2.f,
                                  (const float4*)Xt, -1.f);
        k_gemm<true, false><<<dim3(3, 640), 256>>>(Xt, pP1, pP2, 192, pWx, pbx, pGx, 192);
        // H-side basis + (z,r) GEMM
        k_prop<<<propGrid, 128>>>((const float4*)pH, (float4*)pP1, 1.f, nullptr, 0.f);
        k_prop<<<propGrid, 128>>>((const float4*)pP1, (float4*)pP2, 2.f,
                                  (const float4*)pH, -1.f);
        k_gemm<true, false><<<dim3(2, 640), 256>>>(pH, pP1, pP2, 192, pWh, pbh, pGh, 128);
        // gates Z, R and HR = H*R
        k_gateZR<<<ewGrid, 256>>>();
        // HR-side basis + hh GEMM
        k_prop<<<propGrid, 128>>>((const float4*)pHR, (float4*)pP1, 1.f, nullptr, 0.f);
        k_prop<<<propGrid, 128>>>((const float4*)pP1, (float4*)pP2, 2.f,
                                  (const float4*)pHR, -1.f);
        k_gemm<true, false><<<dim3(1, 640), 256>>>(pHR, pP1, pP2, 192, pWhh, pbhh, pGhh, 64);
        // H update
        k_gateH<<<ewGrid, 256>>>();
    }

    // ---- MLP head: H reshaped to [4096, 1280] ----
    k_gemm<false, true><<<dim3(10, 32), 256>>>(pH, nullptr, nullptr, 1280, W1, b1, pM1, 640);
    k_gemm<false, true><<<dim3(5, 32), 256>>>(pM1, nullptr, nullptr, 640, W2, b2, pM2, 320);
    k_out<<<512, 256>>>(pM2, W3, b3, out);
}